// round 1
// baseline (speedup 1.0000x reference)
#include <cuda_runtime.h>
#include <math.h>

// SkewSymMatrixExp: out[b] = expm(S_b), S_b 64x64 skew-symmetric scattered from
// S_vec[b] (2016 = 64*63/2 strict-upper entries, row-major; upper = -v, lower = +v).
//
// Method: scaling & squaring. B = S / 2^4, degree-12 Taylor via Paterson-Stockmeyer
// (powers B2,B3,B4; two chunk matmuls), then 4 squarings. 9 matmuls of 64^3 fp32.
// One CTA per matrix, all work in shared memory.

#define LDP 68              // row pitch in floats (64 + 4 pad, keeps 16B alignment)
#define MATF (64 * LDP)     // floats per smem matrix buffer

static __device__ __forceinline__ int tri_off(int i) {
    // number of strict-upper pairs before row i: i*(127-i)/2
    return (i * (127 - i)) >> 1;
}

// C = A * B, all 64x64 row-major with pitch LDP in shared memory.
// 256 threads: 16x16 grid, each thread computes a 4x4 tile.
static __device__ __forceinline__ void mm64(
    float* __restrict__ C, const float* __restrict__ A, const float* __restrict__ B)
{
    const int tx = threadIdx.x & 15;
    const int ty = threadIdx.x >> 4;
    const int r0 = ty << 2;
    const int c0 = tx << 2;

    const float* A0 = A + r0 * LDP;
    const float* A1 = A0 + LDP;
    const float* A2 = A1 + LDP;
    const float* A3 = A2 + LDP;
    const float* Bc = B + c0;

    float acc[4][4];
#pragma unroll
    for (int i = 0; i < 4; i++)
#pragma unroll
        for (int j = 0; j < 4; j++) acc[i][j] = 0.f;

#pragma unroll 8
    for (int k = 0; k < 64; k++) {
        float4 bv = *reinterpret_cast<const float4*>(Bc + k * LDP);
        float a0 = A0[k];
        float a1 = A1[k];
        float a2 = A2[k];
        float a3 = A3[k];
        acc[0][0] += a0 * bv.x; acc[0][1] += a0 * bv.y; acc[0][2] += a0 * bv.z; acc[0][3] += a0 * bv.w;
        acc[1][0] += a1 * bv.x; acc[1][1] += a1 * bv.y; acc[1][2] += a1 * bv.z; acc[1][3] += a1 * bv.w;
        acc[2][0] += a2 * bv.x; acc[2][1] += a2 * bv.y; acc[2][2] += a2 * bv.z; acc[2][3] += a2 * bv.w;
        acc[3][0] += a3 * bv.x; acc[3][1] += a3 * bv.y; acc[3][2] += a3 * bv.z; acc[3][3] += a3 * bv.w;
    }

#pragma unroll
    for (int i = 0; i < 4; i++) {
        float4 o = make_float4(acc[i][0], acc[i][1], acc[i][2], acc[i][3]);
        *reinterpret_cast<float4*>(C + (r0 + i) * LDP + c0) = o;
    }
}

// dst = cI*I + c1*B + c2*B2 + c3*B3 + cX*X   (elementwise, 64x64)
static __device__ __forceinline__ void eval_chunk(
    float* __restrict__ dst,
    const float* __restrict__ B, const float* __restrict__ B2,
    const float* __restrict__ B3, const float* __restrict__ X,
    float cI, float c1, float c2, float c3, float cX)
{
    const int tid = threadIdx.x;
#pragma unroll
    for (int t = 0; t < 16; t++) {
        int idx = tid + t * 256;
        int r = idx >> 6;
        int c = idx & 63;
        int off = r * LDP + c;
        float val = c1 * B[off] + c2 * B2[off] + c3 * B3[off] + cX * X[off];
        if (r == c) val += cI;
        dst[off] = val;
    }
}

__global__ __launch_bounds__(256, 2)
void SkewSymMatrixExp_kernel(const float* __restrict__ Svec, float* __restrict__ out)
{
    extern __shared__ float sm[];
    float* sB  = sm;
    float* sB2 = sB  + MATF;
    float* sB3 = sB2 + MATF;
    float* sB4 = sB3 + MATF;
    float* sT1 = sB4 + MATF;
    float* sT2 = sT1 + MATF;

    const int tid = threadIdx.x;
    const int b = blockIdx.x;
    const float* v = Svec + (size_t)b * 2016;

    // zero B (includes pad columns)
    for (int idx = tid; idx < MATF; idx += 256) sB[idx] = 0.f;
    __syncthreads();

    // scatter: B[i][j] = -v[n]/16, B[j][i] = +v[n]/16, (i,j) strict upper row-major
    const float scl = 0.0625f;  // 1/2^4
    for (int n = tid; n < 2016; n += 256) {
        int i = (int)((127.0f - sqrtf(16129.0f - 8.0f * (float)n)) * 0.5f);
        if (i < 0) i = 0;
        if (i > 62) i = 62;
        while (tri_off(i + 1) <= n) ++i;
        while (tri_off(i) > n) --i;
        int j = i + 1 + (n - tri_off(i));
        float val = v[n] * scl;
        sB[i * LDP + j] = -val;
        sB[j * LDP + i] =  val;
    }
    __syncthreads();

    // powers
    mm64(sB2, sB, sB);
    __syncthreads();
    mm64(sB3, sB2, sB);   // independent outputs, shared (already-synced) inputs
    mm64(sB4, sB2, sB2);
    __syncthreads();

    // Taylor coefficients 1/k!
    const float C3  = 1.6666667e-1f;
    const float C4  = 4.1666668e-2f;
    const float C5  = 8.3333333e-3f;
    const float C6  = 1.3888889e-3f;
    const float C7  = 1.9841270e-4f;
    const float C8  = 2.4801587e-5f;
    const float C9  = 2.7557319e-6f;
    const float C10 = 2.7557319e-7f;
    const float C11 = 2.5052108e-8f;
    const float C12 = 2.0876757e-9f;

    // PS evaluation: T = Q0 + B4*(Q1 + B4*(Q2 + C12*B4))
    eval_chunk(sT1, sB, sB2, sB3, sB4, C8, C9, C10, C11, C12);
    __syncthreads();
    mm64(sT2, sB4, sT1);
    __syncthreads();
    eval_chunk(sT1, sB, sB2, sB3, sT2, C4, C5, C6, C7, 1.0f);
    __syncthreads();
    mm64(sT2, sB4, sT1);
    __syncthreads();
    eval_chunk(sT1, sB, sB2, sB3, sT2, 1.0f, 1.0f, 0.5f, C3, 1.0f);
    __syncthreads();

    // 4 squarings (ping-pong)
    mm64(sT2, sT1, sT1); __syncthreads();
    mm64(sT1, sT2, sT2); __syncthreads();
    mm64(sT2, sT1, sT1); __syncthreads();
    mm64(sT1, sT2, sT2); __syncthreads();

    // write result (coalesced float4 stores)
    float* o = out + (size_t)b * 4096;
    const int tx = tid & 15;
    const int ty = tid >> 4;
    const int r0 = ty << 2;
    const int c0 = tx << 2;
#pragma unroll
    for (int i = 0; i < 4; i++) {
        float4 val = *reinterpret_cast<const float4*>(sT1 + (r0 + i) * LDP + c0);
        *reinterpret_cast<float4*>(o + (r0 + i) * 64 + c0) = val;
    }
}

extern "C" void kernel_launch(void* const* d_in, const int* in_sizes, int n_in,
                              void* d_out, int out_size)
{
    const float* svec = (const float*)d_in[0];
    float* out = (float*)d_out;
    const int batch = in_sizes[0] / 2016;

    const int smem_bytes = 6 * MATF * sizeof(float);  // 104448 B
    cudaFuncSetAttribute(SkewSymMatrixExp_kernel,
                         cudaFuncAttributeMaxDynamicSharedMemorySize, smem_bytes);
    SkewSymMatrixExp_kernel<<<batch, 256, smem_bytes>>>(svec, out);
}